// round 4
// baseline (speedup 1.0000x reference)
#include <cuda_runtime.h>
#include <cuda_bf16.h>
#include <stdint.h>

#define NN   100000
#define EE   1600000
#define CIN  128
#define CHID 64
#define COUT 40

// Scratch (static __device__ arrays — no allocation allowed)
__device__ int    g_oddnz;          // nonzero odd words seen (int64 test)
__device__ int    g_intok;          // words valid as int32 node id
__device__ int    g_fltok;          // words valid as float32 node id
__device__ int    g_dtype;          // 0=int32, 1=int64, 2=float32
__device__ int    g_src[EE];
__device__ int    g_dst[EE];
__device__ int    g_cnt[NN];        // in-degree (excl self loop)
__device__ int    g_rowstart[NN];   // CSR row offsets
__device__ int    g_fillpos[NN];    // atomic cursors for CSR fill
__device__ int    g_bsum[128];      // block sums for scan
__device__ int    g_eidx[EE];       // CSR column (source) array
__device__ float  g_dinv[NN];
__device__ float4 g_h1 [(size_t)NN * CHID / 4];
__device__ float4 g_hag[(size_t)NN * CHID / 4];
__device__ float4 g_h2 [(size_t)NN * COUT / 4];

#define SCAN_BLK 1024
#define PROBE_N  4096   // sampled 8-byte pairs

// ---------------------------------------------------------------------------
// 0) init: zero counts + probe counters
__global__ void k_init(int n) {
    int i = blockIdx.x * blockDim.x + threadIdx.x;
    if (i == 0) { g_oddnz = 0; g_intok = 0; g_fltok = 0; g_dtype = 0; }
    if (i < n) g_cnt[i] = 0;
}

// 0b) dtype probe over a sample of the raw edge buffer.
//  - int64 (values < 2^31): odd 32-bit words are all zero.
//  - float32 node ids: as-float integral and in [0, n); as-int huge.
//  - int32 node ids: as-int in [0, n).
__global__ void k_probe(const unsigned* __restrict__ p, int npairs, int n) {
    int i = blockIdx.x * blockDim.x + threadIdx.x;
    if (i >= npairs) return;
    unsigned lo = p[2 * i];
    unsigned hi = p[2 * i + 1];
    if (hi != 0) atomicAdd(&g_oddnz, 1);
    int iv = (int)lo;
    if (iv >= 0 && iv < n) atomicAdd(&g_intok, 1);
    float f = __int_as_float(iv);
    if (f >= 0.0f && f < (float)n && f == floorf(f)) atomicAdd(&g_fltok, 1);
}

__global__ void k_decide() {
    if (g_oddnz == 0)            g_dtype = 1;   // int64
    else if (g_fltok > g_intok)  g_dtype = 2;   // float32
    else                         g_dtype = 0;   // int32
}

// 0c) convert to clamped int32 src/dst
__global__ void k_convert(const void* __restrict__ p, int E, int n) {
    int e = blockIdx.x * blockDim.x + threadIdx.x;
    if (e >= E) return;
    int dt = g_dtype;
    int s, d;
    if (dt == 1) {
        const long long* q = (const long long*)p;
        s = (int)q[e]; d = (int)q[(size_t)E + e];
    } else if (dt == 2) {
        const float* q = (const float*)p;
        s = (int)q[e]; d = (int)q[(size_t)E + e];
    } else {
        const int* q = (const int*)p;
        s = q[e]; d = q[(size_t)E + e];
    }
    // defensive clamp: no interpretation may ever produce a wild write
    s = min(max(s, 0), n - 1);
    d = min(max(d, 0), n - 1);
    g_src[e] = s;
    g_dst[e] = d;
}

// 1) count in-degree per target
__global__ void k_count(int E) {
    int e = blockIdx.x * blockDim.x + threadIdx.x;
    if (e < E) atomicAdd(&g_cnt[g_dst[e]], 1);
}

// 2a) per-block exclusive scan
__global__ void k_scan1(int n) {
    __shared__ int s[2][SCAN_BLK];
    int t = threadIdx.x;
    int idx = blockIdx.x * SCAN_BLK + t;
    int v = (idx < n) ? g_cnt[idx] : 0;
    s[0][t] = v;
    __syncthreads();
    int cur = 0;
    for (int off = 1; off < SCAN_BLK; off <<= 1) {
        int nxt = cur ^ 1;
        int add = (t >= off) ? s[cur][t - off] : 0;
        s[nxt][t] = s[cur][t] + add;
        __syncthreads();
        cur = nxt;
    }
    if (idx < n) g_rowstart[idx] = s[cur][t] - v;
    if (t == SCAN_BLK - 1) g_bsum[blockIdx.x] = s[cur][t];
}

// 2b) serial exclusive scan of <=128 block sums
__global__ void k_scan2(int nb) {
    if (threadIdx.x == 0 && blockIdx.x == 0) {
        int run = 0;
        for (int i = 0; i < nb; i++) { int t = g_bsum[i]; g_bsum[i] = run; run += t; }
    }
}

// 2c) add block offsets; init fill cursors; dinv = rsqrt(deg+1)
__global__ void k_scan3(int n) {
    int idx = blockIdx.x * blockDim.x + threadIdx.x;
    if (idx >= n) return;
    int rs = g_rowstart[idx] + g_bsum[idx / SCAN_BLK];
    g_rowstart[idx] = rs;
    g_fillpos[idx]  = rs;
    g_dinv[idx] = rsqrtf((float)g_cnt[idx] + 1.0f);
}

// 3) CSR fill
__global__ void k_fill(int E) {
    int e = blockIdx.x * blockDim.x + threadIdx.x;
    if (e >= E) return;
    int pos = atomicAdd(&g_fillpos[g_dst[e]], 1);
    if (pos >= 0 && pos < E) g_eidx[pos] = g_src[e];
}

// ---------------------------------------------------------------------------
// GEMM1: g_h1 = x @ W1   (M x 128) @ (128 x 64). One thread per row.
__global__ void k_gemm1(const float* __restrict__ x, const float* __restrict__ W, int M) {
    __shared__ __align__(16) float Ws[CIN * CHID];     // 32 KB
    for (int i = threadIdx.x; i < CIN * CHID; i += blockDim.x) Ws[i] = W[i];
    __syncthreads();

    int row = blockIdx.x * blockDim.x + threadIdx.x;
    if (row >= M) return;

    float acc[CHID];
    #pragma unroll
    for (int c = 0; c < CHID; c++) acc[c] = 0.0f;

    const float* a = x + (size_t)row * CIN;
    for (int k = 0; k < CIN; k++) {
        float xk = a[k];
        const float* w = &Ws[k * CHID];
        #pragma unroll
        for (int c = 0; c < CHID; c++) acc[c] += xk * w[c];
    }
    float4* o4 = &g_h1[(size_t)row * (CHID / 4)];
    #pragma unroll
    for (int c = 0; c < CHID / 4; c++)
        o4[c] = make_float4(acc[4*c], acc[4*c+1], acc[4*c+2], acc[4*c+3]);
}

// GEMM2: g_h2 = relu(g_hag) @ W2   (M x 64) @ (64 x 40)
__global__ void k_gemm2(const float* __restrict__ W, int M) {
    __shared__ __align__(16) float Ws[CHID * COUT];    // 10 KB
    for (int i = threadIdx.x; i < CHID * COUT; i += blockDim.x) Ws[i] = W[i];
    __syncthreads();

    int row = blockIdx.x * blockDim.x + threadIdx.x;
    if (row >= M) return;

    float acc[COUT];
    #pragma unroll
    for (int c = 0; c < COUT; c++) acc[c] = 0.0f;

    const float4* a4 = &g_hag[(size_t)row * (CHID / 4)];
    for (int k4 = 0; k4 < CHID / 4; k4++) {
        float4 xv = a4[k4];
        xv.x = fmaxf(xv.x, 0.0f); xv.y = fmaxf(xv.y, 0.0f);
        xv.z = fmaxf(xv.z, 0.0f); xv.w = fmaxf(xv.w, 0.0f);
        #pragma unroll
        for (int j = 0; j < 4; j++) {
            float xk = (j == 0) ? xv.x : (j == 1) ? xv.y : (j == 2) ? xv.z : xv.w;
            const float* w = &Ws[(4 * k4 + j) * COUT];
            #pragma unroll
            for (int c = 0; c < COUT; c++) acc[c] += xk * w[c];
        }
    }
    float4* o4 = &g_h2[(size_t)row * (COUT / 4)];
    #pragma unroll
    for (int c = 0; c < COUT / 4; c++)
        o4[c] = make_float4(acc[4*c], acc[4*c+1], acc[4*c+2], acc[4*c+3]);
}

// ---------------------------------------------------------------------------
// Gather layer 1: hag[i] = b1 + dinv[i]^2*h1[i] + sum_{s in N(i)} dinv[s]*dinv[i]*h1[s]
// blockDim = (16, 16)
__global__ void k_gather1(const float* __restrict__ b1, int M, int E) {
    int i = blockIdx.x * blockDim.y + threadIdx.y;
    if (i >= M) return;
    int c = threadIdx.x;                    // 0..15
    float di = g_dinv[i];
    float4 b = ((const float4*)b1)[c];
    float4 v = g_h1[(size_t)i * (CHID/4) + c];
    float s = di * di;
    float4 acc = make_float4(v.x * s + b.x, v.y * s + b.y, v.z * s + b.z, v.w * s + b.w);
    int start = g_rowstart[i];
    int num   = min(g_cnt[i], E - start);
    for (int j = 0; j < num; j++) {
        int src = g_eidx[start + j];
        float w = g_dinv[src] * di;
        float4 u = g_h1[(size_t)src * (CHID/4) + c];
        acc.x += u.x * w; acc.y += u.y * w; acc.z += u.z * w; acc.w += u.w * w;
    }
    g_hag[(size_t)i * (CHID/4) + c] = acc;
}

// Gather layer 2 -> d_out. blockDim = (10, 25)
__global__ void k_gather2(const float* __restrict__ b2, float* __restrict__ out, int M, int E) {
    int i = blockIdx.x * blockDim.y + threadIdx.y;
    if (i >= M) return;
    int c = threadIdx.x;                    // 0..9
    float di = g_dinv[i];
    float4 b = ((const float4*)b2)[c];
    float4 v = g_h2[(size_t)i * (COUT/4) + c];
    float s = di * di;
    float4 acc = make_float4(v.x * s + b.x, v.y * s + b.y, v.z * s + b.z, v.w * s + b.w);
    int start = g_rowstart[i];
    int num   = min(g_cnt[i], E - start);
    for (int j = 0; j < num; j++) {
        int src = g_eidx[start + j];
        float w = g_dinv[src] * di;
        float4 u = g_h2[(size_t)src * (COUT/4) + c];
        acc.x += u.x * w; acc.y += u.y * w; acc.z += u.z * w; acc.w += u.w * w;
    }
    ((float4*)out)[(size_t)i * (COUT/4) + c] = acc;
}

// ---------------------------------------------------------------------------
extern "C" void kernel_launch(void* const* d_in, const int* in_sizes, int n_in,
                              void* d_out, int out_size) {
    int M = out_size / COUT;                 // 100000

    // Identify inputs by element count (ordering-proof; all sizes distinct):
    //   x: M*CIN   edges: 2*E   W1: CIN*CHID   b1: CHID   W2: CHID*COUT   b2: COUT
    const float* x  = nullptr;
    const float* W1 = nullptr;
    const float* b1 = nullptr;
    const float* W2 = nullptr;
    const float* b2 = nullptr;
    const void*  ei = nullptr;
    int eiElems = 0;
    for (int i = 0; i < n_in; i++) {
        int s = in_sizes[i];
        if      (s == M * CIN)      x  = (const float*)d_in[i];
        else if (s == CIN * CHID)   W1 = (const float*)d_in[i];
        else if (s == CHID)         b1 = (const float*)d_in[i];
        else if (s == CHID * COUT)  W2 = (const float*)d_in[i];
        else if (s == COUT)         b2 = (const float*)d_in[i];
        else { ei = d_in[i]; eiElems = s; }
    }
    if (!x || !W1 || !b1 || !W2 || !b2 || !ei) return;  // contract mismatch; do nothing safe

    int E = eiElems / 2;
    if (E > EE) E = EE;
    if (M > NN) M = NN;
    int nb = (M + SCAN_BLK - 1) / SCAN_BLK;

    float* out = (float*)d_out;

    // dtype probe + convert + CSR build
    k_init<<<(M + 255) / 256, 256>>>(M);
    {
        int npairs = (E < PROBE_N) ? E : PROBE_N;
        k_probe<<<(npairs + 255) / 256, 256>>>((const unsigned*)ei, npairs, M);
    }
    k_decide<<<1, 1>>>();
    k_convert<<<(E + 255) / 256, 256>>>(ei, E, M);
    k_count<<<(E + 255) / 256, 256>>>(E);
    k_scan1<<<nb, SCAN_BLK>>>(M);
    k_scan2<<<1, 32>>>(nb);
    k_scan3<<<(M + 255) / 256, 256>>>(M);
    k_fill<<<(E + 255) / 256, 256>>>(E);

    // layer 1
    k_gemm1<<<(M + 255) / 256, 256>>>(x, W1, M);
    {
        dim3 bd(16, 16);
        k_gather1<<<(M + 15) / 16, bd>>>(b1, M, E);
    }

    // layer 2
    k_gemm2<<<(M + 255) / 256, 256>>>(W2, M);
    {
        dim3 bd(10, 25);
        k_gather2<<<(M + 24) / 25, bd>>>(b2, out, M, E);
    }
}

// round 5
// speedup vs baseline: 1.2119x; 1.2119x over previous
#include <cuda_runtime.h>
#include <cuda_bf16.h>
#include <stdint.h>

#define NN   100000
#define EE   1600000
#define CIN  128
#define CHID 64
#define COUT 40

// Scratch (static __device__ arrays — no allocation allowed)
__device__ int    g_oddnz;          // nonzero odd words seen (int64 test)
__device__ int    g_intok;          // words valid as int32 node id
__device__ int    g_fltok;          // words valid as float32 node id
__device__ int    g_dtype;          // 0=int32, 1=int64, 2=float32
__device__ int    g_cnt[NN];        // in-degree (excl self loop)
__device__ int    g_rowstart[NN];   // CSR row offsets
__device__ int    g_fillpos[NN];    // atomic cursors for CSR fill
__device__ int    g_bsum[128];      // block sums for scan
__device__ int    g_eidx[EE];       // CSR column (source) array
__device__ float  g_dinv[NN];
__device__ float4 g_h1 [(size_t)NN * CHID / 4];
__device__ float4 g_hag[(size_t)NN * CHID / 4];
__device__ float4 g_h2 [(size_t)NN * COUT / 4];

#define SCAN_BLK 1024
#define PROBE_N  4096

// ---------------------------------------------------------------------------
// packed f32x2 FMA: d = a * b + d   (2 FMAs per issue slot on sm_103a)
__device__ __forceinline__ void ffma2(unsigned long long& d,
                                      unsigned long long a,
                                      unsigned long long b) {
    asm volatile("fma.rn.f32x2 %0, %1, %2, %0;" : "+l"(d) : "l"(a), "l"(b));
}
__device__ __forceinline__ unsigned long long pack2(float lo, float hi) {
    unsigned long long r;
    asm("mov.b64 %0, {%1, %2};" : "=l"(r) : "f"(lo), "f"(hi));
    return r;
}

// decode one node id from the raw edge buffer under the probed dtype
__device__ __forceinline__ int decode_id(const void* p, size_t idx, int dt, int n) {
    int v;
    if (dt == 1)      v = (int)((const long long*)p)[idx];
    else if (dt == 2) v = (int)((const float*)p)[idx];
    else              v = ((const int*)p)[idx];
    return min(max(v, 0), n - 1);
}

// ---------------------------------------------------------------------------
// 0) init: zero counts + probe counters
__global__ void k_init(int n) {
    int i = blockIdx.x * blockDim.x + threadIdx.x;
    if (i == 0) { g_oddnz = 0; g_intok = 0; g_fltok = 0; g_dtype = 0; }
    if (i < n) g_cnt[i] = 0;
}

// 0b) dtype probe over a sample of the raw edge buffer
__global__ void k_probe(const unsigned* __restrict__ p, int npairs, int n) {
    int i = blockIdx.x * blockDim.x + threadIdx.x;
    if (i >= npairs) return;
    unsigned lo = p[2 * i];
    unsigned hi = p[2 * i + 1];
    if (hi != 0) atomicAdd(&g_oddnz, 1);
    int iv = (int)lo;
    if (iv >= 0 && iv < n) atomicAdd(&g_intok, 1);
    float f = __int_as_float(iv);
    if (f >= 0.0f && f < (float)n && f == floorf(f)) atomicAdd(&g_fltok, 1);
}

__global__ void k_decide() {
    if (g_oddnz == 0)            g_dtype = 1;   // int64
    else if (g_fltok > g_intok)  g_dtype = 2;   // float32
    else                         g_dtype = 0;   // int32
}

// 1) decode dst + count in-degree (fused; no src/dst materialization)
__global__ void k_count(const void* __restrict__ p, int E, int n) {
    int e = blockIdx.x * blockDim.x + threadIdx.x;
    if (e >= E) return;
    int dt = g_dtype;
    int d = decode_id(p, (size_t)E + e, dt, n);
    atomicAdd(&g_cnt[d], 1);
}

// 2a) per-block exclusive scan
__global__ void k_scan1(int n) {
    __shared__ int s[2][SCAN_BLK];
    int t = threadIdx.x;
    int idx = blockIdx.x * SCAN_BLK + t;
    int v = (idx < n) ? g_cnt[idx] : 0;
    s[0][t] = v;
    __syncthreads();
    int cur = 0;
    for (int off = 1; off < SCAN_BLK; off <<= 1) {
        int nxt = cur ^ 1;
        int add = (t >= off) ? s[cur][t - off] : 0;
        s[nxt][t] = s[cur][t] + add;
        __syncthreads();
        cur = nxt;
    }
    if (idx < n) g_rowstart[idx] = s[cur][t] - v;
    if (t == SCAN_BLK - 1) g_bsum[blockIdx.x] = s[cur][t];
}

// 2b) serial exclusive scan of <=128 block sums
__global__ void k_scan2(int nb) {
    if (threadIdx.x == 0 && blockIdx.x == 0) {
        int run = 0;
        for (int i = 0; i < nb; i++) { int t = g_bsum[i]; g_bsum[i] = run; run += t; }
    }
}

// 2c) add block offsets; init fill cursors; dinv = rsqrt(deg+1)
__global__ void k_scan3(int n) {
    int idx = blockIdx.x * blockDim.x + threadIdx.x;
    if (idx >= n) return;
    int rs = g_rowstart[idx] + g_bsum[idx / SCAN_BLK];
    g_rowstart[idx] = rs;
    g_fillpos[idx]  = rs;
    g_dinv[idx] = rsqrtf((float)g_cnt[idx] + 1.0f);
}

// 3) CSR fill (decode src & dst directly from raw buffer)
__global__ void k_fill(const void* __restrict__ p, int E, int n) {
    int e = blockIdx.x * blockDim.x + threadIdx.x;
    if (e >= E) return;
    int dt = g_dtype;
    int s = decode_id(p, (size_t)e, dt, n);
    int d = decode_id(p, (size_t)E + e, dt, n);
    int pos = atomicAdd(&g_fillpos[d], 1);
    if (pos >= 0 && pos < E) g_eidx[pos] = s;
}

// ---------------------------------------------------------------------------
// GEMM1: g_h1 = x @ W1  (M x 128)@(128 x 64). One thread per row, FFMA2 inner.
__global__ void __launch_bounds__(256) k_gemm1(const float* __restrict__ x,
                                               const float* __restrict__ W, int M) {
    __shared__ __align__(16) float Ws[CIN * CHID];     // 32 KB
    for (int i = threadIdx.x; i < CIN * CHID; i += blockDim.x) Ws[i] = W[i];
    __syncthreads();

    int row = blockIdx.x * blockDim.x + threadIdx.x;
    if (row >= M) return;

    unsigned long long acc[CHID / 2];                  // 32 packed pairs
    #pragma unroll
    for (int c = 0; c < CHID / 2; c++) acc[c] = 0ull;

    const float4* a4 = (const float4*)(x + (size_t)row * CIN);
    for (int k4 = 0; k4 < CIN / 4; k4++) {
        float4 xv = __ldg(a4 + k4);
        #pragma unroll
        for (int j = 0; j < 4; j++) {
            float xk = (j == 0) ? xv.x : (j == 1) ? xv.y : (j == 2) ? xv.z : xv.w;
            unsigned long long xp = pack2(xk, xk);
            const unsigned long long* w2 =
                (const unsigned long long*)&Ws[(4 * k4 + j) * CHID];
            #pragma unroll
            for (int c = 0; c < CHID / 2; c++) ffma2(acc[c], xp, w2[c]);
        }
    }
    ulonglong2* o = (ulonglong2*)&g_h1[(size_t)row * (CHID / 4)];
    #pragma unroll
    for (int c = 0; c < CHID / 4; c++)
        o[c] = make_ulonglong2(acc[2 * c], acc[2 * c + 1]);
}

// GEMM2: g_h2 = relu(g_hag) @ W2  (M x 64)@(64 x 40), FFMA2 inner.
__global__ void __launch_bounds__(256) k_gemm2(const float* __restrict__ W, int M) {
    __shared__ __align__(16) float Ws[CHID * COUT];    // 10 KB
    for (int i = threadIdx.x; i < CHID * COUT; i += blockDim.x) Ws[i] = W[i];
    __syncthreads();

    int row = blockIdx.x * blockDim.x + threadIdx.x;
    if (row >= M) return;

    unsigned long long acc[COUT / 2];                  // 20 packed pairs
    #pragma unroll
    for (int c = 0; c < COUT / 2; c++) acc[c] = 0ull;

    const float4* a4 = (const float4*)&g_hag[(size_t)row * (CHID / 4)];
    for (int k4 = 0; k4 < CHID / 4; k4++) {
        float4 xv = a4[k4];
        xv.x = fmaxf(xv.x, 0.0f); xv.y = fmaxf(xv.y, 0.0f);
        xv.z = fmaxf(xv.z, 0.0f); xv.w = fmaxf(xv.w, 0.0f);
        #pragma unroll
        for (int j = 0; j < 4; j++) {
            float xk = (j == 0) ? xv.x : (j == 1) ? xv.y : (j == 2) ? xv.z : xv.w;
            unsigned long long xp = pack2(xk, xk);
            const unsigned long long* w2 =
                (const unsigned long long*)&Ws[(4 * k4 + j) * COUT];
            #pragma unroll
            for (int c = 0; c < COUT / 2; c++) ffma2(acc[c], xp, w2[c]);
        }
    }
    ulonglong2* o = (ulonglong2*)&g_h2[(size_t)row * (COUT / 4)];
    #pragma unroll
    for (int c = 0; c < COUT / 4; c++)
        o[c] = make_ulonglong2(acc[2 * c], acc[2 * c + 1]);
}

// ---------------------------------------------------------------------------
// Gather layer 1: hag[i] = b1 + dinv[i]^2*h1[i] + sum_{s in N(i)} dinv[s]*dinv[i]*h1[s]
// blockDim = (16, 16)
__global__ void k_gather1(const float* __restrict__ b1, int M, int E) {
    int i = blockIdx.x * blockDim.y + threadIdx.y;
    if (i >= M) return;
    int c = threadIdx.x;                    // 0..15
    float di = g_dinv[i];
    float4 b = ((const float4*)b1)[c];
    float4 v = g_h1[(size_t)i * (CHID/4) + c];
    float s = di * di;
    float4 acc = make_float4(v.x * s + b.x, v.y * s + b.y, v.z * s + b.z, v.w * s + b.w);
    int start = g_rowstart[i];
    int num   = min(g_cnt[i], E - start);
    for (int j = 0; j < num; j++) {
        int src = g_eidx[start + j];
        float w = g_dinv[src] * di;
        float4 u = g_h1[(size_t)src * (CHID/4) + c];
        acc.x += u.x * w; acc.y += u.y * w; acc.z += u.z * w; acc.w += u.w * w;
    }
    g_hag[(size_t)i * (CHID/4) + c] = acc;
}

// Gather layer 2 -> d_out. blockDim = (10, 25)
__global__ void k_gather2(const float* __restrict__ b2, float* __restrict__ out, int M, int E) {
    int i = blockIdx.x * blockDim.y + threadIdx.y;
    if (i >= M) return;
    int c = threadIdx.x;                    // 0..9
    float di = g_dinv[i];
    float4 b = ((const float4*)b2)[c];
    float4 v = g_h2[(size_t)i * (COUT/4) + c];
    float s = di * di;
    float4 acc = make_float4(v.x * s + b.x, v.y * s + b.y, v.z * s + b.z, v.w * s + b.w);
    int start = g_rowstart[i];
    int num   = min(g_cnt[i], E - start);
    for (int j = 0; j < num; j++) {
        int src = g_eidx[start + j];
        float w = g_dinv[src] * di;
        float4 u = g_h2[(size_t)src * (COUT/4) + c];
        acc.x += u.x * w; acc.y += u.y * w; acc.z += u.z * w; acc.w += u.w * w;
    }
    ((float4*)out)[(size_t)i * (COUT/4) + c] = acc;
}

// ---------------------------------------------------------------------------
extern "C" void kernel_launch(void* const* d_in, const int* in_sizes, int n_in,
                              void* d_out, int out_size) {
    int M = out_size / COUT;                 // 100000

    // Identify inputs by element count (ordering-proof; all sizes distinct)
    const float* x  = nullptr;
    const float* W1 = nullptr;
    const float* b1 = nullptr;
    const float* W2 = nullptr;
    const float* b2 = nullptr;
    const void*  ei = nullptr;
    int eiElems = 0;
    for (int i = 0; i < n_in; i++) {
        int s = in_sizes[i];
        if      (s == M * CIN)      x  = (const float*)d_in[i];
        else if (s == CIN * CHID)   W1 = (const float*)d_in[i];
        else if (s == CHID)         b1 = (const float*)d_in[i];
        else if (s == CHID * COUT)  W2 = (const float*)d_in[i];
        else if (s == COUT)         b2 = (const float*)d_in[i];
        else { ei = d_in[i]; eiElems = s; }
    }
    if (!x || !W1 || !b1 || !W2 || !b2 || !ei) return;

    int E = eiElems / 2;
    if (E > EE) E = EE;
    if (M > NN) M = NN;
    int nb = (M + SCAN_BLK - 1) / SCAN_BLK;

    float* out = (float*)d_out;

    // dtype probe + CSR build (decode fused into count/fill)
    k_init<<<(M + 255) / 256, 256>>>(M);
    {
        int npairs = (E < PROBE_N) ? E : PROBE_N;
        k_probe<<<(npairs + 255) / 256, 256>>>((const unsigned*)ei, npairs, M);
    }
    k_decide<<<1, 1>>>();
    k_count<<<(E + 255) / 256, 256>>>(ei, E, M);
    k_scan1<<<nb, SCAN_BLK>>>(M);
    k_scan2<<<1, 32>>>(nb);
    k_scan3<<<(M + 255) / 256, 256>>>(M);
    k_fill<<<(E + 255) / 256, 256>>>(ei, E, M);

    // layer 1
    k_gemm1<<<(M + 255) / 256, 256>>>(x, W1, M);
    {
        dim3 bd(16, 16);
        k_gather1<<<(M + 15) / 16, bd>>>(b1, M, E);
    }

    // layer 2
    k_gemm2<<<(M + 255) / 256, 256>>>(W2, M);
    {
        dim3 bd(10, 25);
        k_gather2<<<(M + 24) / 25, bd>>>(b2, out, M, E);
    }
}